// round 1
// baseline (speedup 1.0000x reference)
#include <cuda_runtime.h>
#include <cstdint>

// Problem constants (fixed shapes)
#define B_ 2
#define H_ 8
#define S_ 2048
#define D_ 64
#define BH_ (B_ * H_)
#define OUT_OFF ((size_t)B_ * H_ * S_ * D_)   // 2,097,152 floats: output tensor, then weights

// Precomputed bias per (head, relative-position + 2048)
__device__ float g_bias_lut[H_ * 2 * S_];     // 8 * 4096

// ---------------------------------------------------------------------------
// Kernel 0: T5 relative-position bias LUT.
// bucket thresholds are the EXACT integer floor of
//   8 + floor( log(a/8)/log(16) * 8 ),  a = |rel|
// boundaries: a in [8,12)->8 [12,16)->9 [16,23)->10 [23,32)->11
//             [32,46)->12 [46,64)->13 [64,91)->14 [91,inf)->15
// ---------------------------------------------------------------------------
__global__ void bias_lut_kernel(const float* __restrict__ bias_table) {
    int idx = blockIdx.x * blockDim.x + threadIdx.x;   // 0 .. 32767
    if (idx >= H_ * 2 * S_) return;
    int h   = idx >> 12;          // /4096
    int r   = idx & 4095;
    int rel = r - 2048;           // k - q
    int bucket = (rel > 0) ? 16 : 0;
    int a = rel < 0 ? -rel : rel;
    int add;
    if      (a <  8) add = a;
    else if (a < 12) add = 8;
    else if (a < 16) add = 9;
    else if (a < 23) add = 10;
    else if (a < 32) add = 11;
    else if (a < 46) add = 12;
    else if (a < 64) add = 13;
    else if (a < 91) add = 14;
    else             add = 15;
    bucket += add;
    g_bias_lut[idx] = bias_table[bucket * H_ + h];
}

// ---------------------------------------------------------------------------
// Kernel 1: logits = Q K^T / 8 + bias + mask*-1e9, written raw into the
// weights region of d_out. 64x64 tile per block, 4x4 register micro-tile.
// ---------------------------------------------------------------------------
__global__ __launch_bounds__(256) void logits_kernel(
    const float* __restrict__ Q, const float* __restrict__ K,
    const int* __restrict__ mask, float* __restrict__ out)
{
    __shared__ float Qs[64][68];   // [d][row], padded (68 floats = 272B, 16B-aligned rows)
    __shared__ float Ks[64][68];   // [d][col]

    int bh = blockIdx.z;
    int q0 = blockIdx.y * 64;
    int k0 = blockIdx.x * 64;
    int b  = bh >> 3;
    int h  = bh & 7;

    const float* Qp = Q + (size_t)bh * S_ * D_;
    const float* Kp = K + (size_t)bh * S_ * D_;

    int t = threadIdx.x;
    #pragma unroll
    for (int i = 0; i < 16; i++) {
        int idx = t + i * 256;            // 0..4095
        int r = idx >> 6, d = idx & 63;   // coalesced over d
        Qs[d][r] = Qp[(size_t)(q0 + r) * D_ + d];
        Ks[d][r] = Kp[(size_t)(k0 + r) * D_ + d];
    }
    __syncthreads();

    int tx = t & 15, ty = t >> 4;
    float acc[4][4] = {};

    #pragma unroll 16
    for (int kk = 0; kk < 64; kk++) {
        float4 a  = *(const float4*)&Qs[kk][ty * 4];
        float4 bb = *(const float4*)&Ks[kk][tx * 4];
        acc[0][0] += a.x * bb.x; acc[0][1] += a.x * bb.y; acc[0][2] += a.x * bb.z; acc[0][3] += a.x * bb.w;
        acc[1][0] += a.y * bb.x; acc[1][1] += a.y * bb.y; acc[1][2] += a.y * bb.z; acc[1][3] += a.y * bb.w;
        acc[2][0] += a.z * bb.x; acc[2][1] += a.z * bb.y; acc[2][2] += a.z * bb.z; acc[2][3] += a.z * bb.w;
        acc[3][0] += a.w * bb.x; acc[3][1] += a.w * bb.y; acc[3][2] += a.w * bb.z; acc[3][3] += a.w * bb.w;
    }

    // epilogue: scale + bias + mask, vectorized store
    float mv[4];
    #pragma unroll
    for (int j = 0; j < 4; j++)
        mv[j] = -1e9f * (float)mask[b * S_ + k0 + tx * 4 + j];

    float* wbase = out + OUT_OFF + (size_t)bh * S_ * S_;
    const float* lut = g_bias_lut + h * 4096;
    #pragma unroll
    for (int i = 0; i < 4; i++) {
        int q = q0 + ty * 4 + i;
        int kbase = k0 + tx * 4;
        float4 v;
        v.x = acc[i][0] * 0.125f + lut[kbase + 0 - q + 2048] + mv[0];
        v.y = acc[i][1] * 0.125f + lut[kbase + 1 - q + 2048] + mv[1];
        v.z = acc[i][2] * 0.125f + lut[kbase + 2 - q + 2048] + mv[2];
        v.w = acc[i][3] * 0.125f + lut[kbase + 3 - q + 2048] + mv[3];
        *(float4*)&wbase[(size_t)q * S_ + kbase] = v;
    }
}

// ---------------------------------------------------------------------------
// Kernel 2: in-place row softmax over the 2048-wide weight rows.
// One block (256 threads) per row; each thread owns 8 elements (2x float4).
// ---------------------------------------------------------------------------
__global__ __launch_bounds__(256) void softmax_kernel(float* __restrict__ w)
{
    __shared__ float redmax[8];
    __shared__ float redsum[8];

    float* p = w + OUT_OFF + (size_t)blockIdx.x * S_;
    int t = threadIdx.x;

    float4 v0 = reinterpret_cast<float4*>(p)[t];
    float4 v1 = reinterpret_cast<float4*>(p)[t + 256];

    float m = fmaxf(fmaxf(fmaxf(v0.x, v0.y), fmaxf(v0.z, v0.w)),
                    fmaxf(fmaxf(v1.x, v1.y), fmaxf(v1.z, v1.w)));
    #pragma unroll
    for (int o = 16; o; o >>= 1) m = fmaxf(m, __shfl_xor_sync(0xffffffffu, m, o));
    if ((t & 31) == 0) redmax[t >> 5] = m;
    __syncthreads();
    m = redmax[0];
    #pragma unroll
    for (int i = 1; i < 8; i++) m = fmaxf(m, redmax[i]);

    v0.x = expf(v0.x - m); v0.y = expf(v0.y - m); v0.z = expf(v0.z - m); v0.w = expf(v0.w - m);
    v1.x = expf(v1.x - m); v1.y = expf(v1.y - m); v1.z = expf(v1.z - m); v1.w = expf(v1.w - m);

    float s = (v0.x + v0.y) + (v0.z + v0.w) + (v1.x + v1.y) + (v1.z + v1.w);
    #pragma unroll
    for (int o = 16; o; o >>= 1) s += __shfl_xor_sync(0xffffffffu, s, o);
    if ((t & 31) == 0) redsum[t >> 5] = s;
    __syncthreads();
    s = 0.f;
    #pragma unroll
    for (int i = 0; i < 8; i++) s += redsum[i];

    float inv = 1.0f / s;
    v0.x *= inv; v0.y *= inv; v0.z *= inv; v0.w *= inv;
    v1.x *= inv; v1.y *= inv; v1.z *= inv; v1.w *= inv;

    reinterpret_cast<float4*>(p)[t]       = v0;
    reinterpret_cast<float4*>(p)[t + 256] = v1;
}

// ---------------------------------------------------------------------------
// Kernel 3: output = P @ V.  M=2048 (tiled 64), N=64 (full), K=2048 (64-chunks).
// ---------------------------------------------------------------------------
__global__ __launch_bounds__(256) void av_kernel(
    const float* __restrict__ W, const float* __restrict__ V, float* __restrict__ out)
{
    __shared__ float Ps[64][68];   // [kk][row]
    __shared__ float Vs[64][68];   // [kk][d]

    int bh = blockIdx.z;
    int q0 = blockIdx.y * 64;

    const float* Wp = W + OUT_OFF + (size_t)bh * S_ * S_;
    const float* Vp = V + (size_t)bh * S_ * D_;

    int t = threadIdx.x;
    int tx = t & 15, ty = t >> 4;
    float acc[4][4] = {};

    for (int kc = 0; kc < S_; kc += 64) {
        #pragma unroll
        for (int i = 0; i < 16; i++) {
            int idx = t + i * 256;
            int r = idx >> 6, kk = idx & 63;      // coalesced over kk
            Ps[kk][r] = Wp[(size_t)(q0 + r) * S_ + kc + kk];
        }
        #pragma unroll
        for (int i = 0; i < 4; i++) {
            int idx4 = t + i * 256;               // 1024 float4s
            int row = idx4 >> 4, c4 = idx4 & 15;  // coalesced
            *(float4*)&Vs[row][c4 * 4] = *(const float4*)&Vp[(size_t)(kc + row) * D_ + c4 * 4];
        }
        __syncthreads();

        #pragma unroll 16
        for (int kk = 0; kk < 64; kk++) {
            float4 a  = *(const float4*)&Ps[kk][ty * 4];
            float4 bv = *(const float4*)&Vs[kk][tx * 4];
            acc[0][0] += a.x * bv.x; acc[0][1] += a.x * bv.y; acc[0][2] += a.x * bv.z; acc[0][3] += a.x * bv.w;
            acc[1][0] += a.y * bv.x; acc[1][1] += a.y * bv.y; acc[1][2] += a.y * bv.z; acc[1][3] += a.y * bv.w;
            acc[2][0] += a.z * bv.x; acc[2][1] += a.z * bv.y; acc[2][2] += a.z * bv.z; acc[2][3] += a.z * bv.w;
            acc[3][0] += a.w * bv.x; acc[3][1] += a.w * bv.y; acc[3][2] += a.w * bv.z; acc[3][3] += a.w * bv.w;
        }
        __syncthreads();
    }

    #pragma unroll
    for (int i = 0; i < 4; i++) {
        int q = q0 + ty * 4 + i;
        float4 v = make_float4(acc[i][0], acc[i][1], acc[i][2], acc[i][3]);
        *(float4*)&out[((size_t)bh * S_ + q) * D_ + tx * 4] = v;
    }
}

// ---------------------------------------------------------------------------
extern "C" void kernel_launch(void* const* d_in, const int* in_sizes, int n_in,
                              void* d_out, int out_size)
{
    const float* Q    = (const float*)d_in[0];
    const float* K    = (const float*)d_in[1];
    const float* V    = (const float*)d_in[2];
    const int*   mask = (const int*)d_in[3];
    const float* bt   = (const float*)d_in[4];
    float* out = (float*)d_out;

    bias_lut_kernel<<<32, 1024>>>(bt);

    dim3 g1(S_ / 64, S_ / 64, BH_);   // (32, 32, 16)
    logits_kernel<<<g1, 256>>>(Q, K, mask, out);

    softmax_kernel<<<BH_ * S_, 256>>>(out);

    dim3 g2(1, S_ / 64, BH_);         // (1, 32, 16)
    av_kernel<<<g2, 256>>>(out, V, out);
}

// round 2
// speedup vs baseline: 1.1519x; 1.1519x over previous
#include <cuda_runtime.h>
#include <cstdint>

#define B_ 2
#define H_ 8
#define S_ 2048
#define D_ 64
#define BH_ (B_ * H_)
#define OUT_OFF ((size_t)B_ * H_ * S_ * D_)   // output tensor first, then weights

__device__ float g_bias_lut[H_ * 2 * S_];     // 8 * 4096

// ---- packed f32x2 helpers ---------------------------------------------------
__device__ __forceinline__ unsigned long long pk2(float lo, float hi) {
    unsigned long long r;
    asm("mov.b64 %0, {%1, %2};" : "=l"(r) : "f"(lo), "f"(hi));
    return r;
}
__device__ __forceinline__ void fma2(unsigned long long& d, unsigned long long a, unsigned long long b) {
    asm("fma.rn.f32x2 %0, %1, %2, %0;" : "+l"(d) : "l"(a), "l"(b));
}
__device__ __forceinline__ void upk2(unsigned long long v, float& lo, float& hi) {
    asm("mov.b64 {%0, %1}, %2;" : "=f"(lo), "=f"(hi) : "l"(v));
}

// smem swizzle: XOR row-block within a transposed tile (multiple of 8 floats)
#define SWZ(kk) ((((kk) >> 2) & 3) * 8)

// ---------------------------------------------------------------------------
// Kernel 0: T5 relative-position bias LUT (exact integer bucket thresholds)
// ---------------------------------------------------------------------------
__global__ void bias_lut_kernel(const float* __restrict__ bias_table) {
    int idx = blockIdx.x * blockDim.x + threadIdx.x;
    if (idx >= H_ * 2 * S_) return;
    int h   = idx >> 12;
    int r   = idx & 4095;
    int rel = r - 2048;
    int bucket = (rel > 0) ? 16 : 0;
    int a = rel < 0 ? -rel : rel;
    int add;
    if      (a <  8) add = a;
    else if (a < 12) add = 8;
    else if (a < 16) add = 9;
    else if (a < 23) add = 10;
    else if (a < 32) add = 11;
    else if (a < 46) add = 12;
    else if (a < 64) add = 13;
    else if (a < 91) add = 14;
    else             add = 15;
    g_bias_lut[idx] = bias_table[(bucket + add) * H_ + h];
}

// ---------------------------------------------------------------------------
// Kernel 1: logits = Q K^T / 8 + bias + mask*-1e9.
// 128x128 tile, 256 threads, 8x8 per thread, packed f32x2 FMAs.
// Dynamic smem: Qs[64][128] + Ks[64][128] transposed ([d][row]) w/ XOR swizzle.
// ---------------------------------------------------------------------------
__global__ __launch_bounds__(256) void logits_kernel(
    const float* __restrict__ Q, const float* __restrict__ K,
    const int* __restrict__ mask, float* __restrict__ out)
{
    extern __shared__ float smem[];
    float* Qs = smem;                 // [kk][row^swz], stride 128
    float* Ks = smem + 64 * 128;      // [kk][col^swz], stride 128

    int bh = blockIdx.z;
    int q0 = blockIdx.y * 128;
    int k0 = blockIdx.x * 128;
    int b  = bh >> 3;
    int h  = bh & 7;

    const float* Qp = Q + (size_t)bh * S_ * D_;
    const float* Kp = K + (size_t)bh * S_ * D_;

    int t = threadIdx.x;

    // load + transpose: 128 rows x 64 d  (2048 float4 per tensor, 8 per thread)
    #pragma unroll
    for (int i = 0; i < 8; i++) {
        int idx4 = t + i * 256;
        int row = idx4 >> 4;          // 0..127
        int c4  = idx4 & 15;          // d-segment
        float4 qv = *(const float4*)&Qp[(size_t)(q0 + row) * D_ + c4 * 4];
        float4 kv = *(const float4*)&Kp[(size_t)(k0 + row) * D_ + c4 * 4];
        #pragma unroll
        for (int j = 0; j < 4; j++) {
            int kk = c4 * 4 + j;
            int pc = row ^ SWZ(kk);
            float* q4 = &Qs[kk * 128 + pc];
            float* k4 = &Ks[kk * 128 + pc];
            *q4 = j == 0 ? qv.x : j == 1 ? qv.y : j == 2 ? qv.z : qv.w;
            *k4 = j == 0 ? kv.x : j == 1 ? kv.y : j == 2 ? kv.z : kv.w;
        }
    }
    __syncthreads();

    int tx = t & 15, ty = t >> 4;
    unsigned long long acc2[8][4];
    #pragma unroll
    for (int i = 0; i < 8; i++)
        #pragma unroll
        for (int j = 0; j < 4; j++) acc2[i][j] = 0ULL;

    #pragma unroll 8
    for (int kk = 0; kk < 64; kk++) {
        int am = (ty * 8) ^ SWZ(kk);
        int bm = (tx * 8) ^ SWZ(kk);
        float4 a0 = *(const float4*)&Qs[kk * 128 + am];
        float4 a1 = *(const float4*)&Qs[kk * 128 + am + 4];
        float4 b0 = *(const float4*)&Ks[kk * 128 + bm];
        float4 b1 = *(const float4*)&Ks[kk * 128 + bm + 4];
        unsigned long long bp[4] = { pk2(b0.x, b0.y), pk2(b0.z, b0.w),
                                     pk2(b1.x, b1.y), pk2(b1.z, b1.w) };
        float av[8] = {a0.x, a0.y, a0.z, a0.w, a1.x, a1.y, a1.z, a1.w};
        #pragma unroll
        for (int i = 0; i < 8; i++) {
            unsigned long long ad = pk2(av[i], av[i]);
            fma2(acc2[i][0], ad, bp[0]);
            fma2(acc2[i][1], ad, bp[1]);
            fma2(acc2[i][2], ad, bp[2]);
            fma2(acc2[i][3], ad, bp[3]);
        }
    }

    // epilogue
    int kbase = k0 + tx * 8;
    float mv[8];
    #pragma unroll
    for (int j = 0; j < 8; j++)
        mv[j] = -1e9f * (float)mask[b * S_ + kbase + j];

    float* wbase = out + OUT_OFF + (size_t)bh * S_ * S_;
    const float* lut = g_bias_lut + h * 4096;
    #pragma unroll
    for (int i = 0; i < 8; i++) {
        int q = q0 + ty * 8 + i;
        float c[8];
        #pragma unroll
        for (int j = 0; j < 4; j++) upk2(acc2[i][j], c[2 * j], c[2 * j + 1]);
        float4 v0, v1;
        v0.x = c[0] * 0.125f + lut[kbase + 0 - q + 2048] + mv[0];
        v0.y = c[1] * 0.125f + lut[kbase + 1 - q + 2048] + mv[1];
        v0.z = c[2] * 0.125f + lut[kbase + 2 - q + 2048] + mv[2];
        v0.w = c[3] * 0.125f + lut[kbase + 3 - q + 2048] + mv[3];
        v1.x = c[4] * 0.125f + lut[kbase + 4 - q + 2048] + mv[4];
        v1.y = c[5] * 0.125f + lut[kbase + 5 - q + 2048] + mv[5];
        v1.z = c[6] * 0.125f + lut[kbase + 6 - q + 2048] + mv[6];
        v1.w = c[7] * 0.125f + lut[kbase + 7 - q + 2048] + mv[7];
        *(float4*)&wbase[(size_t)q * S_ + kbase]     = v0;
        *(float4*)&wbase[(size_t)q * S_ + kbase + 4] = v1;
    }
}

// ---------------------------------------------------------------------------
// Kernel 2: in-place row softmax (2048-wide rows), one 256-thread block/row.
// ---------------------------------------------------------------------------
__global__ __launch_bounds__(256) void softmax_kernel(float* __restrict__ w)
{
    __shared__ float redmax[8];
    __shared__ float redsum[8];

    float* p = w + OUT_OFF + (size_t)blockIdx.x * S_;
    int t = threadIdx.x;

    float4 v0 = reinterpret_cast<float4*>(p)[t];
    float4 v1 = reinterpret_cast<float4*>(p)[t + 256];

    float m = fmaxf(fmaxf(fmaxf(v0.x, v0.y), fmaxf(v0.z, v0.w)),
                    fmaxf(fmaxf(v1.x, v1.y), fmaxf(v1.z, v1.w)));
    #pragma unroll
    for (int o = 16; o; o >>= 1) m = fmaxf(m, __shfl_xor_sync(0xffffffffu, m, o));
    if ((t & 31) == 0) redmax[t >> 5] = m;
    __syncthreads();
    m = redmax[0];
    #pragma unroll
    for (int i = 1; i < 8; i++) m = fmaxf(m, redmax[i]);

    v0.x = expf(v0.x - m); v0.y = expf(v0.y - m); v0.z = expf(v0.z - m); v0.w = expf(v0.w - m);
    v1.x = expf(v1.x - m); v1.y = expf(v1.y - m); v1.z = expf(v1.z - m); v1.w = expf(v1.w - m);

    float s = (v0.x + v0.y) + (v0.z + v0.w) + (v1.x + v1.y) + (v1.z + v1.w);
    #pragma unroll
    for (int o = 16; o; o >>= 1) s += __shfl_xor_sync(0xffffffffu, s, o);
    if ((t & 31) == 0) redsum[t >> 5] = s;
    __syncthreads();
    s = 0.f;
    #pragma unroll
    for (int i = 0; i < 8; i++) s += redsum[i];

    float inv = 1.0f / s;
    v0.x *= inv; v0.y *= inv; v0.z *= inv; v0.w *= inv;
    v1.x *= inv; v1.y *= inv; v1.z *= inv; v1.w *= inv;

    reinterpret_cast<float4*>(p)[t]       = v0;
    reinterpret_cast<float4*>(p)[t + 256] = v1;
}

// ---------------------------------------------------------------------------
// Kernel 3: output = P @ V. 64x64 tile, 128 threads, 8x4 per thread, f32x2.
// ---------------------------------------------------------------------------
__global__ __launch_bounds__(128) void av_kernel(
    const float* __restrict__ W, const float* __restrict__ V, float* __restrict__ out)
{
    __shared__ float Ps[64 * 64];   // [kk][row^swz], stride 64
    __shared__ float Vs[64 * 64];   // [kk][d], natural

    int bh = blockIdx.y;
    int q0 = blockIdx.x * 64;

    const float* Wp = W + OUT_OFF + (size_t)bh * S_ * S_;
    const float* Vp = V + (size_t)bh * S_ * D_;

    int t = threadIdx.x;
    int tx = t & 15, ty = t >> 4;

    unsigned long long acc2[8][2];
    #pragma unroll
    for (int i = 0; i < 8; i++) { acc2[i][0] = 0ULL; acc2[i][1] = 0ULL; }

    for (int kc = 0; kc < S_; kc += 64) {
        #pragma unroll
        for (int i = 0; i < 8; i++) {
            int idx4 = t + i * 128;
            int r  = idx4 >> 4;       // 0..63 (q-row within tile)
            int c4 = idx4 & 15;       // k-chunk segment
            float4 wv = *(const float4*)&Wp[(size_t)(q0 + r) * S_ + kc + c4 * 4];
            #pragma unroll
            for (int j = 0; j < 4; j++) {
                int kk = c4 * 4 + j;
                Ps[kk * 64 + (r ^ SWZ(kk))] =
                    j == 0 ? wv.x : j == 1 ? wv.y : j == 2 ? wv.z : wv.w;
            }
            // V: natural layout, coalesced float4
            float4 vv = *(const float4*)&Vp[(size_t)(kc + r) * D_ + c4 * 4];
            *(float4*)&Vs[r * 64 + c4 * 4] = vv;
        }
        __syncthreads();

        #pragma unroll 8
        for (int kk = 0; kk < 64; kk++) {
            int am = (ty * 8) ^ SWZ(kk);
            float4 a0 = *(const float4*)&Ps[kk * 64 + am];
            float4 a1 = *(const float4*)&Ps[kk * 64 + am + 4];
            float4 bv = *(const float4*)&Vs[kk * 64 + tx * 4];
            unsigned long long bp0 = pk2(bv.x, bv.y);
            unsigned long long bp1 = pk2(bv.z, bv.w);
            float av[8] = {a0.x, a0.y, a0.z, a0.w, a1.x, a1.y, a1.z, a1.w};
            #pragma unroll
            for (int i = 0; i < 8; i++) {
                unsigned long long ad = pk2(av[i], av[i]);
                fma2(acc2[i][0], ad, bp0);
                fma2(acc2[i][1], ad, bp1);
            }
        }
        __syncthreads();
    }

    #pragma unroll
    for (int i = 0; i < 8; i++) {
        int q = q0 + ty * 8 + i;
        float4 v;
        upk2(acc2[i][0], v.x, v.y);
        upk2(acc2[i][1], v.z, v.w);
        *(float4*)&out[((size_t)bh * S_ + q) * D_ + tx * 4] = v;
    }
}

// ---------------------------------------------------------------------------
extern "C" void kernel_launch(void* const* d_in, const int* in_sizes, int n_in,
                              void* d_out, int out_size)
{
    const float* Q    = (const float*)d_in[0];
    const float* K    = (const float*)d_in[1];
    const float* V    = (const float*)d_in[2];
    const int*   mask = (const int*)d_in[3];
    const float* bt   = (const float*)d_in[4];
    float* out = (float*)d_out;

    static_assert(2 * 64 * 128 * sizeof(float) == 65536, "");
    cudaFuncSetAttribute(logits_kernel, cudaFuncAttributeMaxDynamicSharedMemorySize, 65536);

    bias_lut_kernel<<<32, 1024>>>(bt);

    dim3 g1(S_ / 128, S_ / 128, BH_);   // (16, 16, 16)
    logits_kernel<<<g1, 256, 65536>>>(Q, K, mask, out);

    softmax_kernel<<<BH_ * S_, 256>>>(out);

    dim3 g2(S_ / 64, BH_);              // (32, 16)
    av_kernel<<<g2, 128>>>(out, V, out);
}